// round 5
// baseline (speedup 1.0000x reference)
#include <cuda_runtime.h>
#include <cstdint>
#include <math.h>

#define T_STEPS 1000
#define BATCH   4096
#define T_EXACT 220
#define CHUNK   10
#define NCHUNK_EXACT (T_EXACT / CHUNK)   // 22

#define MEANS_ELEMS ((size_t)T_STEPS * BATCH * 8)

#define NB_MEAN  32
#define NB_BCAST 855
#define NB_TOTAL 888                      // 148 SMs x 6 blocks, one wave
#define THREADS  256
#define FULLMASK 0xffffffffu
#define NSDA     9                        // Phi^(2^9) = Phi^512

#define NFROZEN  (T_STEPS - T_EXACT)      // 780
#define NEXTRA   (NB_BCAST - NFROZEN)     // 75 early-exact tiles in pass 0
#define NPASS1   (T_EXACT - NEXTRA)       // 145 exact tiles in pass 1

// exact-region coefficients: A_t = M_t@F (A_0=M_0) [64] + K_t [32]; up_cov U_t [64]
__device__ __align__(16) float g_MK[T_EXACT * 96];
__device__ __align__(16) float g_U [T_EXACT * 64];
// steady-state coefficients (frozen region)
__device__ __align__(16) float g_sMK[96];
__device__ __align__(16) float g_sU [64];
__device__ int g_ready;    // exact steps published (multiples of 10)
__device__ int g_sflag;    // 0 = pending, 1 = steady valid, 2 = use exact row fallback

__device__ __forceinline__ int ld_acq(const int* p) {
    int v; asm volatile("ld.global.acquire.gpu.b32 %0, [%1];" : "=r"(v) : "l"(p)); return v;
}
__device__ __forceinline__ void st_rel(int* p, int v) {
    asm volatile("st.global.release.gpu.b32 [%0], %1;" :: "l"(p), "r"(v) : "memory");
}

// cofactor (r,c) of a 4x4, element index l = r*4+c (float and double variants)
template <typename T>
__device__ __forceinline__ double cof4t(const T* S, int l) {
    int r = l >> 2, c = l & 3;
    int ra[3], ca[3];
    int n = 0;
    #pragma unroll
    for (int x = 0; x < 4; x++) if (x != r) ra[n++] = x;
    n = 0;
    #pragma unroll
    for (int x = 0; x < 4; x++) if (x != c) ca[n++] = x;
    double m00 = S[ra[0]*4+ca[0]], m01 = S[ra[0]*4+ca[1]], m02 = S[ra[0]*4+ca[2]];
    double m10 = S[ra[1]*4+ca[0]], m11 = S[ra[1]*4+ca[1]], m12 = S[ra[1]*4+ca[2]];
    double m20 = S[ra[2]*4+ca[0]], m21 = S[ra[2]*4+ca[1]], m22 = S[ra[2]*4+ca[2]];
    double d = m00*(m11*m22 - m12*m21) - m01*(m10*m22 - m12*m20) + m02*(m10*m21 - m11*m20);
    return ((r + c) & 1) ? -d : d;
}
__device__ __forceinline__ float cof4f(const float* S, int l) { return (float)cof4t<float>(S, l); }

// warp-collective 8x8 fp64 inverse, Gauss-Jordan with partial pivoting.
// lane l<8 holds row l; result written to Ainv (lanes <8).
__device__ void inv8x8_d(const double* A, double* Ainv, int l) {
    double rA[8], rI[8];
    #pragma unroll
    for (int j = 0; j < 8; j++) {
        rA[j] = (l < 8) ? A[l*8 + j] : 0.0;
        rI[j] = (l == j) ? 1.0 : 0.0;
    }
    #pragma unroll 1
    for (int k = 0; k < 8; k++) {
        double cand = (l >= k && l < 8) ? fabs(rA[k]) : -1.0;
        int idx = (l < 8) ? l : 0;
        #pragma unroll
        for (int d = 1; d < 8; d <<= 1) {
            double oc = __shfl_xor_sync(FULLMASK, cand, d);
            int    oi = __shfl_xor_sync(FULLMASK, idx,  d);
            if (oc > cand || (oc == cand && oi < idx)) { cand = oc; idx = oi; }
        }
        const int piv = __shfl_sync(FULLMASK, idx, 0);   // lane 0 reduced over rows 0-7
        const int src = (l == k) ? piv : ((l == piv) ? k : l);
        #pragma unroll
        for (int j = 0; j < 8; j++) {
            rA[j] = __shfl_sync(FULLMASK, rA[j], src);
            rI[j] = __shfl_sync(FULLMASK, rI[j], src);
        }
        double pA[8], pI[8];
        #pragma unroll
        for (int j = 0; j < 8; j++) {
            pA[j] = __shfl_sync(FULLMASK, rA[j], k);
            pI[j] = __shfl_sync(FULLMASK, rI[j], k);
        }
        const double inv = 1.0 / pA[k];
        if (l == k) {
            #pragma unroll
            for (int j = 0; j < 8; j++) { rA[j] = pA[j]*inv; rI[j] = pI[j]*inv; }
        } else {
            const double f = rA[k] * inv;
            #pragma unroll
            for (int j = 0; j < 8; j++) { rA[j] -= f*pA[j]; rI[j] -= f*pI[j]; }
        }
    }
    if (l < 8) {
        #pragma unroll
        for (int j = 0; j < 8; j++) Ainv[l*8 + j] = rI[j];
    }
}

// ---------------------------------------------------------------------------
// warp 1 of block 0: steady state via STRUCTURE-PRESERVING DOUBLING (fp64).
// Phi(P) = W + V P (I+UP)^-1 V^T ; doubling: T=(I+WU)^-1,
//   W += (VTW) V^T ; U += V^T (UTV) ; V = (VT) V.    All iterates bounded.
// ---------------------------------------------------------------------------
__device__ void sda_warp(int l,
    const float* Fs, const float* Hs, const float* Qs, const float* Rs,
    double* dW, double* dV, double* dU,
    double* dA, double* dT, double* dB, double* dC, double* dD, double* dE)
{
    const int i0 = l >> 3, j = l & 7;    // two 8x8 rows per lane: i0, i0+4
    const int qi = l >> 2, qj = l & 3;

    // ---- init: W=Q, V=F, U = H^T Rinv H  (Rinv via 4x4 cofactors)
    if (l < 16) dA[l] = cof4t<float>(Rs, l);
    __syncwarp();
    {
        const double det  = (double)Rs[0]*dA[0] + (double)Rs[1]*dA[1]
                          + (double)Rs[2]*dA[2] + (double)Rs[3]*dA[3];
        const double rdet = 1.0 / det;
        double e0 = 0.0, e1 = 0.0;
        #pragma unroll
        for (int a = 0; a < 4; a++) {
            double t0 = 0.0;                         // (Rinv H)[a][j]
            #pragma unroll
            for (int b = 0; b < 4; b++) t0 += dA[b*4 + a] * (double)Hs[b*8 + j];
            t0 *= rdet;
            e0 += (double)Hs[a*8 + i0]     * t0;
            e1 += (double)Hs[a*8 + i0 + 4] * t0;
        }
        dU[i0*8 + j] = e0;  dU[(i0+4)*8 + j] = e1;
        dW[l] = Qs[l];  dW[32 + l] = Qs[32 + l];
        dV[l] = Fs[l];  dV[32 + l] = Fs[32 + l];
    }
    __syncwarp();

    // ---- NSDA doublings
    #pragma unroll 1
    for (int it = 0; it < NSDA; it++) {
        {   // dA = I + W@U
            double s0 = 0.0, s1 = 0.0;
            #pragma unroll
            for (int k = 0; k < 8; k++) {
                const double ukj = dU[k*8 + j];
                s0 += dW[i0*8 + k]     * ukj;
                s1 += dW[(i0+4)*8 + k] * ukj;
            }
            dA[i0*8 + j]     = s0 + (i0 == j     ? 1.0 : 0.0);
            dA[(i0+4)*8 + j] = s1 + (i0 + 4 == j ? 1.0 : 0.0);
        }
        __syncwarp();
        inv8x8_d(dA, dT, l);
        __syncwarp();
        {   // dB = V@T ; dD = U@T
            double b0 = 0.0, b1 = 0.0, d0 = 0.0, d1 = 0.0;
            #pragma unroll
            for (int k = 0; k < 8; k++) {
                const double tkj = dT[k*8 + j];
                b0 += dV[i0*8 + k]     * tkj;
                b1 += dV[(i0+4)*8 + k] * tkj;
                d0 += dU[i0*8 + k]     * tkj;
                d1 += dU[(i0+4)*8 + k] * tkj;
            }
            dB[i0*8 + j] = b0;  dB[(i0+4)*8 + j] = b1;
            dD[i0*8 + j] = d0;  dD[(i0+4)*8 + j] = d1;
        }
        __syncwarp();
        {   // dC = dB@W ; dE = dD@V
            double c0 = 0.0, c1 = 0.0, e0 = 0.0, e1 = 0.0;
            #pragma unroll
            for (int k = 0; k < 8; k++) {
                const double wkj = dW[k*8 + j], vkj = dV[k*8 + j];
                c0 += dB[i0*8 + k]     * wkj;
                c1 += dB[(i0+4)*8 + k] * wkj;
                e0 += dD[i0*8 + k]     * vkj;
                e1 += dD[(i0+4)*8 + k] * vkj;
            }
            dC[i0*8 + j] = c0;  dC[(i0+4)*8 + j] = c1;
            dE[i0*8 + j] = e0;  dE[(i0+4)*8 + j] = e1;
        }
        __syncwarp();
        {   // updates in registers, then store
            double wn0 = dW[i0*8 + j], wn1 = dW[(i0+4)*8 + j];
            double un0 = dU[i0*8 + j], un1 = dU[(i0+4)*8 + j];
            double vn0 = 0.0, vn1 = 0.0;
            #pragma unroll
            for (int k = 0; k < 8; k++) {
                wn0 += dC[i0*8 + k]     * dV[j*8 + k];   // + (VTW) V^T
                wn1 += dC[(i0+4)*8 + k] * dV[j*8 + k];
                un0 += dV[k*8 + i0]     * dE[k*8 + j];   // + V^T (UTV)
                un1 += dV[k*8 + i0 + 4] * dE[k*8 + j];
                vn0 += dB[i0*8 + k]     * dV[k*8 + j];   // (VT) V
                vn1 += dB[(i0+4)*8 + k] * dV[k*8 + j];
            }
            __syncwarp();
            dW[i0*8 + j] = wn0;  dW[(i0+4)*8 + j] = wn1;
            dU[i0*8 + j] = un0;  dU[(i0+4)*8 + j] = un1;
            dV[i0*8 + j] = vn0;  dV[(i0+4)*8 + j] = vn1;
        }
        __syncwarp();
    }

    // ---- steady coefficients from Pinf = dW (all fp64, mirror exact-step math)
    {   // dA[0..31] = HC = H@Pinf ; dA[32..63] = CHt = Pinf@H^T
        const int hi = l >> 3;
        double s = 0.0, c = 0.0;
        #pragma unroll
        for (int k = 0; k < 8; k++) {
            s += (double)Hs[hi*8 + k] * dW[k*8 + j];
            c += dW[qi*8 + k] * (double)Hs[qj*8 + k];
        }
        dA[l] = s;  dA[32 + l] = c;
    }
    __syncwarp();
    if (l < 16) {   // dB[0..15] = S = HC@H^T + R
        double s = Rs[l];
        #pragma unroll
        for (int k = 0; k < 8; k++) s += dA[(l >> 2)*8 + k] * (double)Hs[(l & 3)*8 + k];
        dB[l] = s;
    }
    __syncwarp();
    if (l < 16) dB[16 + l] = cof4t<double>(dB, l);
    __syncwarp();
    {   // dC[0..31] = K = CHt @ (Cof*rdet)
        const double det  = dB[0]*dB[16] + dB[1]*dB[17] + dB[2]*dB[18] + dB[3]*dB[19];
        const double rdet = 1.0 / det;
        double s = 0.0;
        #pragma unroll
        for (int k = 0; k < 4; k++) s += dA[32 + qi*4 + k] * dB[16 + k*4 + qj];
        dC[l] = s * rdet;
    }
    __syncwarp();
    {   // dD = M2 = I - K@H
        double m0 = 0.0, m1 = 0.0;
        #pragma unroll
        for (int k = 0; k < 4; k++) {
            const double hkj = Hs[k*8 + j];
            m0 += dC[i0*4 + k]     * hkj;
            m1 += dC[(i0+4)*4 + k] * hkj;
        }
        dD[i0*8 + j]     = (i0 == j     ? 1.0 : 0.0) - m0;
        dD[(i0+4)*8 + j] = (i0 + 4 == j ? 1.0 : 0.0) - m1;
    }
    __syncwarp();
    {   // A = M2@F, U = Pinf - K@HC ; cast, sanity-check, publish
        double a0 = 0.0, a1 = 0.0, s0 = 0.0, s1 = 0.0;
        #pragma unroll
        for (int k = 0; k < 8; k++) {
            const double fkj = Fs[k*8 + j];
            a0 += dD[i0*8 + k]     * fkj;
            a1 += dD[(i0+4)*8 + k] * fkj;
        }
        #pragma unroll
        for (int k = 0; k < 4; k++) {
            const double hckj = dA[k*8 + j];
            s0 += dC[i0*4 + k]     * hckj;
            s1 += dC[(i0+4)*4 + k] * hckj;
        }
        const float fa0 = (float)a0, fa1 = (float)a1, fk = (float)dC[l];
        const float fu0 = (float)(dW[i0*8 + j]     - s0);
        const float fu1 = (float)(dW[(i0+4)*8 + j] - s1);
        bool bad = !isfinite(fa0) || !isfinite(fa1) || !isfinite(fk)
                 || !isfinite(fu0) || !isfinite(fu1)
                 || fabsf(fa0) > 100.f || fabsf(fa1) > 100.f || fabsf(fk) > 100.f
                 || fabsf(fu0) > 100.f || fabsf(fu1) > 100.f;
        const unsigned anybad = __ballot_sync(FULLMASK, bad);
        g_sMK[l]      = fa0;
        g_sMK[32 + l] = fa1;
        g_sMK[64 + l] = fk;
        g_sU[l]       = fu0;
        g_sU[32 + l]  = fu1;
        __threadfence();
        if (l == 0) st_rel(&g_sflag, anybad ? 2 : 1);
    }
}

// ---------------------------------------------------------------------------
// The single fused kernel
// ---------------------------------------------------------------------------
__global__ void __launch_bounds__(THREADS, 6) fused_kernel(
    const float* __restrict__ obs,
    const float* __restrict__ F,
    const float* __restrict__ H,
    const float* __restrict__ Q,
    const float* __restrict__ R,
    const float* __restrict__ init_mean,
    const float* __restrict__ init_cov,
    float* __restrict__ out)
{
    __shared__ float coef[CHUNK * 96];
    __shared__ int s_flag;
    // block-0 warp-0 (exact stream) arrays
    __shared__ float P[64], Hs[32], Fs[64], Qs[64], Rs[16];
    __shared__ float HC[32], CHt[32], FP[64], Ssm[16], Cof[16], Ksm[32], W[32];
    __shared__ float Msm[64];
    // block-0 warp-1 (SDA) buffers
    __shared__ double dW[64], dV[64], dU[64], dA[64], dT[64], dB[64], dC[64], dD[64], dE[64];

    const int tid = threadIdx.x;

    if (blockIdx.x == 0) {
        // ---------------- block 0: coefficient producers ----------------
        if (tid < 32) {
            Fs[tid] = F[tid];  Fs[32 + tid] = F[32 + tid];
            Qs[tid] = Q[tid];  Qs[32 + tid] = Q[32 + tid];
            P [tid] = init_cov[tid];  P[32 + tid] = init_cov[32 + tid];
            Hs[tid] = H[tid];
            if (tid < 16) Rs[tid] = R[tid];
        }
        __syncthreads();
        if (tid >= 64) return;

        if (tid >= 32) {
            sda_warp(tid - 32, Fs, Hs, Qs, Rs, dW, dV, dU, dA, dT, dB, dC, dD, dE);
            return;
        }

        // ---- warp 0: exact step stream (T_EXACT steps)  [proven in R3]
        const int l  = tid;
        const int i0 = l >> 3, j = l & 7;
        const int qi = l >> 2, qj = l & 3;

        for (int t = 0; t < T_EXACT; t++) {
            {
                float fp0 = 0.f, fp1 = 0.f, hc = 0.f, cht = 0.f;
                #pragma unroll
                for (int k = 0; k < 8; k++) {
                    const float pkj = P[k*8 + j];
                    fp0 += Fs[i0*8 + k]     * pkj;
                    fp1 += Fs[(i0+4)*8 + k] * pkj;
                    hc  += Hs[i0*8 + k]     * pkj;
                    cht += P[qi*8 + k] * Hs[qj*8 + k];
                }
                FP[l] = fp0;  FP[32 + l] = fp1;
                HC[l] = hc;   CHt[l] = cht;
            }
            __syncwarp();
            if (l < 16) {
                float s = Rs[l];
                #pragma unroll
                for (int k = 0; k < 8; k++) s += HC[(l >> 2)*8 + k] * Hs[(l & 3)*8 + k];
                Ssm[l] = s;
            }
            __syncwarp();
            if (l < 16) Cof[l] = cof4f(Ssm, l);
            __syncwarp();
            {
                float det = Ssm[0]*Cof[0] + Ssm[1]*Cof[1] + Ssm[2]*Cof[2] + Ssm[3]*Cof[3];
                float rdet = 1.0f / det;
                float s = 0.f;
                #pragma unroll
                for (int k = 0; k < 4; k++) s += CHt[qi*4 + k] * Cof[k*4 + qj];
                Ksm[l] = s * rdet;
            }
            __syncwarp();
            float u0, u1;
            {
                float su0 = 0.f, sm0 = 0.f, su1 = 0.f, sm1 = 0.f, w = 0.f;
                #pragma unroll
                for (int k = 0; k < 4; k++) {
                    const float hckj = HC[k*8 + j], hskj = Hs[k*8 + j];
                    su0 += Ksm[i0*4 + k]     * hckj;
                    sm0 += Ksm[i0*4 + k]     * hskj;
                    su1 += Ksm[(i0+4)*4 + k] * hckj;
                    sm1 += Ksm[(i0+4)*4 + k] * hskj;
                }
                #pragma unroll
                for (int k = 0; k < 8; k++) w += Fs[qi*8 + k] * Ksm[k*4 + qj];
                u0 = P[l] - su0;
                u1 = P[32 + l] - su1;
                Msm[l]      = (i0 == j     ? 1.0f : 0.0f) - sm0;
                Msm[32 + l] = (i0 + 4 == j ? 1.0f : 0.0f) - sm1;
                W[l] = w;
            }
            __syncwarp();
            {
                float a0, a1;
                if (t == 0) { a0 = Msm[l];  a1 = Msm[32 + l]; }
                else {
                    a0 = 0.f;  a1 = 0.f;
                    #pragma unroll
                    for (int k = 0; k < 8; k++) {
                        const float fkj = Fs[k*8 + j];
                        a0 += Msm[i0*8 + k]     * fkj;
                        a1 += Msm[(i0+4)*8 + k] * fkj;
                    }
                }
                g_MK[t*96 + l]      = a0;
                g_MK[t*96 + 32 + l] = a1;
                g_MK[t*96 + 64 + l] = Ksm[l];
                g_U [t*64 + l]      = u0;
                g_U [t*64 + 32 + l] = u1;

                const float w00 = W[i0*4+0],     w01 = W[i0*4+1],     w02 = W[i0*4+2],     w03 = W[i0*4+3];
                const float w10 = W[(i0+4)*4+0], w11 = W[(i0+4)*4+1], w12 = W[(i0+4)*4+2], w13 = W[(i0+4)*4+3];
                float p0 = Qs[l], p1 = Qs[32 + l];
                #pragma unroll
                for (int k = 0; k < 8; k++) {
                    const float h0 = HC[k], h1 = HC[8+k], h2 = HC[16+k], h3 = HC[24+k];
                    const float fjk = Fs[j*8 + k];
                    const float fu0 = FP[i0*8 + k]     - (w00*h0 + w01*h1 + w02*h2 + w03*h3);
                    const float fu1 = FP[(i0+4)*8 + k] - (w10*h0 + w11*h1 + w12*h2 + w13*h3);
                    p0 += fu0 * fjk;
                    p1 += fu1 * fjk;
                }
                P[l] = p0;  P[32 + l] = p1;
            }
            __syncwarp();
            if ((t % CHUNK) == CHUNK - 1) {
                __threadfence();
                if (l == 0) st_rel(&g_ready, t + 1);
            }
        }
    } else if (blockIdx.x <= NB_MEAN) {
        // ---------------- mean recursion (2 threads/batch) ----------------
        const int gtid = (blockIdx.x - 1) * THREADS + tid;
        const int b    = gtid >> 1;
        const int half = gtid & 1;

        float st[8];
        #pragma unroll
        for (int i = 0; i < 8; i++) st[i] = init_mean[b*8 + i];

        for (int c = 0; c < T_STEPS / CHUNK; c++) {
            if (c < NCHUNK_EXACT) {
                __syncthreads();
                if (tid == 0)
                    while (ld_acq(&g_ready) < (c + 1) * CHUNK) __nanosleep(128);
                __syncthreads();
                if (tid < CHUNK*24)
                    reinterpret_cast<float4*>(coef)[tid] =
                        reinterpret_cast<const float4*>(&g_MK[c*(CHUNK*96)])[tid];
                __syncthreads();
            } else if (c == NCHUNK_EXACT) {
                __syncthreads();
                if (tid == 0) {
                    int sf;
                    while ((sf = ld_acq(&g_sflag)) == 0) __nanosleep(128);
                    if (sf == 2)
                        while (ld_acq(&g_ready) < T_EXACT) __nanosleep(128);
                    s_flag = sf;
                }
                __syncthreads();
                const float4* csrc = (s_flag == 1)
                    ? reinterpret_cast<const float4*>(g_sMK)
                    : reinterpret_cast<const float4*>(&g_MK[(T_EXACT-1)*96]);
                if (tid < 24)
                    reinterpret_cast<float4*>(coef)[tid] = csrc[tid];
                __syncthreads();
            }
            #pragma unroll
            for (int u = 0; u < CHUNK; u++) {
                const int t = c*CHUNK + u;
                const float* Cs = &coef[(c < NCHUNK_EXACT ? u : 0) * 96];

                const float4 zv = *reinterpret_cast<const float4*>(
                    &obs[((size_t)t*BATCH + b) * 4]);

                float y[4];
                #pragma unroll
                for (int r = 0; r < 4; r++) {
                    const int row = half*4 + r;
                    const float4 a0 = *reinterpret_cast<const float4*>(&Cs[row*8]);
                    const float4 a1 = *reinterpret_cast<const float4*>(&Cs[row*8 + 4]);
                    const float4 kk = *reinterpret_cast<const float4*>(&Cs[64 + row*4]);
                    y[r] = a0.x*st[0] + a0.y*st[1] + a0.z*st[2] + a0.w*st[3]
                         + a1.x*st[4] + a1.y*st[5] + a1.z*st[6] + a1.w*st[7]
                         + kk.x*zv.x + kk.y*zv.y + kk.z*zv.z + kk.w*zv.w;
                }

                __stcs(reinterpret_cast<float4*>(&out[((size_t)t*BATCH + b)*8 + half*4]),
                       make_float4(y[0], y[1], y[2], y[3]));

                const float o0 = __shfl_xor_sync(FULLMASK, y[0], 1);
                const float o1 = __shfl_xor_sync(FULLMASK, y[1], 1);
                const float o2 = __shfl_xor_sync(FULLMASK, y[2], 1);
                const float o3 = __shfl_xor_sync(FULLMASK, y[3], 1);
                st[0] = half ? o0   : y[0];
                st[1] = half ? o1   : y[1];
                st[2] = half ? o2   : y[2];
                st[3] = half ? o3   : y[3];
                st[4] = half ? y[0] : o0;
                st[5] = half ? y[1] : o1;
                st[6] = half ? y[2] : o2;
                st[7] = half ? y[3] : o3;
            }
        }
    } else {
        // ---------------- covariance broadcast (frozen-first) ----------------
        const int i = (int)blockIdx.x - 1 - NB_MEAN;          // [0, NB_BCAST)
        float4* const base = reinterpret_cast<float4*>(out + MEANS_ELEMS);

        #pragma unroll 1
        for (int pass = 0; pass < 2; pass++) {
            int t;
            if (pass == 0)  t = (i < NFROZEN) ? (T_EXACT + i) : (i - NFROZEN);
            else            { if (i >= NPASS1) break;  t = NEXTRA + i; }

            float4 val;
            if (t < T_EXACT) {
                if (tid == 0)
                    while (ld_acq(&g_ready) <= t) __nanosleep(128);
                __syncthreads();
                val = reinterpret_cast<const float4*>(g_U)[t*16 + (tid & 15)];
            } else {
                if (tid == 0) {
                    int sf;
                    while ((sf = ld_acq(&g_sflag)) == 0) __nanosleep(64);
                    if (sf == 2)
                        while (ld_acq(&g_ready) < T_EXACT) __nanosleep(128);
                    s_flag = sf;
                }
                __syncthreads();
                val = (s_flag == 1)
                    ? reinterpret_cast<const float4*>(g_sU)[tid & 15]
                    : reinterpret_cast<const float4*>(g_U)[(T_EXACT-1)*16 + (tid & 15)];
            }

            float4* dst = base + (size_t)t * 65536 + tid;
            #pragma unroll 8
            for (int it = 0; it < 256; it++) {
                __stcs(dst, val);
                dst += THREADS;
            }
            __syncthreads();
        }
    }
}

// ---------------------------------------------------------------------------
extern "C" void kernel_launch(void* const* d_in, const int* in_sizes, int n_in,
                              void* d_out, int out_size)
{
    const float* obs       = (const float*)d_in[0];
    const float* F         = (const float*)d_in[1];
    const float* H         = (const float*)d_in[2];
    const float* Q         = (const float*)d_in[3];
    const float* R         = (const float*)d_in[4];
    const float* init_mean = (const float*)d_in[5];
    const float* init_cov  = (const float*)d_in[6];
    float* out = (float*)d_out;

    fused_kernel<<<NB_TOTAL, THREADS>>>(obs, F, H, Q, R, init_mean, init_cov, out);
}

// round 6
// speedup vs baseline: 1.4950x; 1.4950x over previous
#include <cuda_runtime.h>
#include <cstdint>
#include <math.h>

#define T_STEPS 1000
#define BATCH   4096
#define T_EXACT 220                        // 6 super-steps of 32 + chains
#define CHUNK   10
#define NCHUNK_EXACT 22                    // 220 / 10

#define NSDA     9                         // doublings: Phi^512 for steady state
#define SNAP_IT  5                         // snapshot Phi^32 after 5 doublings
#define SUPW     32
#define NCHAIN   7                         // ceil(220/32); last chain = 28 steps
#define NSUPER   6                         // P_32..P_192 from P_0

#define MEANS_ELEMS ((size_t)T_STEPS * BATCH * 8)
#define NB_MEAN  32
#define NB_TOTAL (NB_MEAN + T_STEPS)       // 1032
#define THREADS  256
#define FULLMASK 0xffffffffu

// rows 0..T_EXACT-1 = exact; row T_EXACT = steady state.
// per row: A_t = M_t@F (A_0 = M_0) [64] + K_t [32]
__device__ __align__(16) float g_MK[(T_EXACT + 1) * 96];
__device__ __align__(16) float g_U [(T_EXACT + 1) * 64];

// cofactor (r,c) of a 4x4, element index l = r*4+c
template <typename T>
__device__ __forceinline__ float cof4t(const T* S, int l) {
    int r = l >> 2, c = l & 3;
    int ra[3], ca[3];
    int n = 0;
    #pragma unroll
    for (int x = 0; x < 4; x++) if (x != r) ra[n++] = x;
    n = 0;
    #pragma unroll
    for (int x = 0; x < 4; x++) if (x != c) ca[n++] = x;
    double m00 = S[ra[0]*4+ca[0]], m01 = S[ra[0]*4+ca[1]], m02 = S[ra[0]*4+ca[2]];
    double m10 = S[ra[1]*4+ca[0]], m11 = S[ra[1]*4+ca[1]], m12 = S[ra[1]*4+ca[2]];
    double m20 = S[ra[2]*4+ca[0]], m21 = S[ra[2]*4+ca[1]], m22 = S[ra[2]*4+ca[2]];
    double d = m00*(m11*m22 - m12*m21) - m01*(m10*m22 - m12*m20) + m02*(m10*m21 - m11*m20);
    return (float)(((r + c) & 1) ? -d : d);
}

// warp-collective fp32 8x8 inverse, Gauss-Jordan + partial pivoting (R5-proven structure)
__device__ void inv8x8_f(const float* A, float* Ainv, int l) {
    float rA[8], rI[8];
    #pragma unroll
    for (int j = 0; j < 8; j++) {
        rA[j] = (l < 8) ? A[l*8 + j] : 0.f;
        rI[j] = (l == j) ? 1.f : 0.f;
    }
    #pragma unroll 1
    for (int k = 0; k < 8; k++) {
        float cand = (l >= k && l < 8) ? fabsf(rA[k]) : -1.f;
        int idx = (l < 8) ? l : 0;
        #pragma unroll
        for (int d = 1; d < 8; d <<= 1) {
            float oc = __shfl_xor_sync(FULLMASK, cand, d);
            int   oi = __shfl_xor_sync(FULLMASK, idx,  d);
            if (oc > cand || (oc == cand && oi < idx)) { cand = oc; idx = oi; }
        }
        const int piv = __shfl_sync(FULLMASK, idx, 0);
        const int src = (l == k) ? piv : ((l == piv) ? k : l);
        #pragma unroll
        for (int j = 0; j < 8; j++) {
            rA[j] = __shfl_sync(FULLMASK, rA[j], src);
            rI[j] = __shfl_sync(FULLMASK, rI[j], src);
        }
        float pA[8], pI[8];
        #pragma unroll
        for (int j = 0; j < 8; j++) {
            pA[j] = __shfl_sync(FULLMASK, rA[j], k);
            pI[j] = __shfl_sync(FULLMASK, rI[j], k);
        }
        const float inv = 1.f / pA[k];
        if (l == k) {
            #pragma unroll
            for (int j = 0; j < 8; j++) { rA[j] = pA[j]*inv; rI[j] = pI[j]*inv; }
        } else {
            const float f = rA[k] * inv;
            #pragma unroll
            for (int j = 0; j < 8; j++) { rA[j] -= f*pA[j]; rI[j] -= f*pI[j]; }
        }
    }
    if (l < 8) {
        #pragma unroll
        for (int j = 0; j < 8; j++) Ainv[l*8 + j] = rI[j];
    }
}

// ---------------------------------------------------------------------------
// Setup kernel (1 block, 8 warps):
//   warp 0: fp32 SDA doublings (steady state, R5-validated recursion) with a
//           Phi^32 snapshot, then 6 super-steps -> restart covs P_{32j};
//   warps 1..7: parallel exact 32-step chains covering t = 0..219.
// Kernel boundary synchronizes with the main kernel — no flags.
// ---------------------------------------------------------------------------
__global__ void __launch_bounds__(256) setup_kernel(
    const float* __restrict__ F,
    const float* __restrict__ H,
    const float* __restrict__ Q,
    const float* __restrict__ R,
    const float* __restrict__ init_cov)
{
    __shared__ float Fs[64], Hs[32], Qs[64], Rs[16];
    __shared__ float sW[64], sV[64], sU[64];               // SDA triple
    __shared__ float W32[64], V32[64], U32[64];            // Phi^32 triple
    __shared__ float phA[64], phT[64], phB[64], phD[64], sPinf[64];
    __shared__ float stHC[32], stCHt[32], stS[16], stCof[16], stK[32], stM[64];
    __shared__ float sP[NCHAIN][64];                       // restart covariances
    __shared__ float cw_all[NCHAIN][288];                  // per-chain scratch

    const int tid = threadIdx.x;
    const int wid = tid >> 5;
    const int l   = tid & 31;

    if (wid == 0) {
        const int i0 = l >> 3, j = l & 7;
        const int qi = l >> 2, qj = l & 3;

        // ---- load inputs
        Fs[l] = F[l];  Fs[32 + l] = F[32 + l];
        Qs[l] = Q[l];  Qs[32 + l] = Q[32 + l];
        Hs[l] = H[l];
        if (l < 16) Rs[l] = R[l];
        sP[0][l] = init_cov[l];  sP[0][32 + l] = init_cov[32 + l];
        __syncwarp();

        // ---- init triple: W=Q, V=F, U = H^T Rinv H
        if (l < 16) stCof[l] = cof4t<float>(Rs, l);
        __syncwarp();
        {
            const float det  = Rs[0]*stCof[0] + Rs[1]*stCof[1] + Rs[2]*stCof[2] + Rs[3]*stCof[3];
            const float rdet = 1.f / det;
            float e0 = 0.f, e1 = 0.f;
            #pragma unroll
            for (int a = 0; a < 4; a++) {
                float t0 = 0.f;
                #pragma unroll
                for (int b = 0; b < 4; b++) t0 += stCof[b*4 + a] * Hs[b*8 + j];
                t0 *= rdet;
                e0 += Hs[a*8 + i0]     * t0;
                e1 += Hs[a*8 + i0 + 4] * t0;
            }
            sU[i0*8 + j] = e0;  sU[(i0+4)*8 + j] = e1;
            sW[l] = Qs[l];  sW[32 + l] = Qs[32 + l];
            sV[l] = Fs[l];  sV[32 + l] = Fs[32 + l];
        }
        __syncwarp();

        // ---- 9 doublings (R5-validated recursion, fp32); snapshot Phi^32
        #pragma unroll 1
        for (int it = 0; it < NSDA; it++) {
            if (it == SNAP_IT) {
                W32[l] = sW[l];  W32[32+l] = sW[32+l];
                V32[l] = sV[l];  V32[32+l] = sV[32+l];
                U32[l] = sU[l];  U32[32+l] = sU[32+l];
                __syncwarp();
            }
            {   // phA = I + W@U
                float s0 = 0.f, s1 = 0.f;
                #pragma unroll
                for (int k = 0; k < 8; k++) {
                    const float ukj = sU[k*8 + j];
                    s0 += sW[i0*8 + k]     * ukj;
                    s1 += sW[(i0+4)*8 + k] * ukj;
                }
                phA[i0*8 + j]     = s0 + (i0 == j     ? 1.f : 0.f);
                phA[(i0+4)*8 + j] = s1 + (i0 + 4 == j ? 1.f : 0.f);
            }
            __syncwarp();
            inv8x8_f(phA, phT, l);
            __syncwarp();
            {   // phB = V@T ; phD = U@T
                float b0 = 0.f, b1 = 0.f, d0 = 0.f, d1 = 0.f;
                #pragma unroll
                for (int k = 0; k < 8; k++) {
                    const float tkj = phT[k*8 + j];
                    b0 += sV[i0*8 + k]     * tkj;
                    b1 += sV[(i0+4)*8 + k] * tkj;
                    d0 += sU[i0*8 + k]     * tkj;
                    d1 += sU[(i0+4)*8 + k] * tkj;
                }
                phB[i0*8 + j] = b0;  phB[(i0+4)*8 + j] = b1;
                phD[i0*8 + j] = d0;  phD[(i0+4)*8 + j] = d1;
            }
            __syncwarp();
            {   // phA = (VT)@W ; phT(overwrite) = (UT)@V
                float c0 = 0.f, c1 = 0.f, e0 = 0.f, e1 = 0.f;
                #pragma unroll
                for (int k = 0; k < 8; k++) {
                    const float wkj = sW[k*8 + j], vkj = sV[k*8 + j];
                    c0 += phB[i0*8 + k]     * wkj;
                    c1 += phB[(i0+4)*8 + k] * wkj;
                    e0 += phD[i0*8 + k]     * vkj;
                    e1 += phD[(i0+4)*8 + k] * vkj;
                }
                __syncwarp();                // phT fully consumed above
                phA[i0*8 + j] = c0;  phA[(i0+4)*8 + j] = c1;
                phT[i0*8 + j] = e0;  phT[(i0+4)*8 + j] = e1;
            }
            __syncwarp();
            {   // W += phA@V^T ; U += V^T@phT ; V = phB@V   (reg-buffered)
                float wn0 = sW[i0*8 + j], wn1 = sW[(i0+4)*8 + j];
                float un0 = sU[i0*8 + j], un1 = sU[(i0+4)*8 + j];
                float vn0 = 0.f, vn1 = 0.f;
                #pragma unroll
                for (int k = 0; k < 8; k++) {
                    wn0 += phA[i0*8 + k]     * sV[j*8 + k];
                    wn1 += phA[(i0+4)*8 + k] * sV[j*8 + k];
                    un0 += sV[k*8 + i0]      * phT[k*8 + j];
                    un1 += sV[k*8 + i0 + 4]  * phT[k*8 + j];
                    vn0 += phB[i0*8 + k]     * sV[k*8 + j];
                    vn1 += phB[(i0+4)*8 + k] * sV[k*8 + j];
                }
                __syncwarp();
                sW[i0*8 + j] = wn0;  sW[(i0+4)*8 + j] = wn1;
                sU[i0*8 + j] = un0;  sU[(i0+4)*8 + j] = un1;
                sV[i0*8 + j] = vn0;  sV[(i0+4)*8 + j] = vn1;
            }
            __syncwarp();
        }

        // ---- Pinf = Phi^512(P0) = W + V P0 (I + U P0)^-1 V^T
        {
            float s0 = 0.f, s1 = 0.f;
            #pragma unroll
            for (int k = 0; k < 8; k++) {
                const float pkj = sP[0][k*8 + j];
                s0 += sU[i0*8 + k]     * pkj;
                s1 += sU[(i0+4)*8 + k] * pkj;
            }
            phA[i0*8 + j]     = s0 + (i0 == j     ? 1.f : 0.f);
            phA[(i0+4)*8 + j] = s1 + (i0 + 4 == j ? 1.f : 0.f);
        }
        __syncwarp();
        inv8x8_f(phA, phT, l);
        __syncwarp();
        {   // phB = P0@T
            float b0 = 0.f, b1 = 0.f;
            #pragma unroll
            for (int k = 0; k < 8; k++) {
                const float tkj = phT[k*8 + j];
                b0 += sP[0][i0*8 + k]     * tkj;
                b1 += sP[0][(i0+4)*8 + k] * tkj;
            }
            phB[i0*8 + j] = b0;  phB[(i0+4)*8 + j] = b1;
        }
        __syncwarp();
        {   // phD = V@phB
            float d0 = 0.f, d1 = 0.f;
            #pragma unroll
            for (int k = 0; k < 8; k++) {
                const float bkj = phB[k*8 + j];
                d0 += sV[i0*8 + k]     * bkj;
                d1 += sV[(i0+4)*8 + k] * bkj;
            }
            phD[i0*8 + j] = d0;  phD[(i0+4)*8 + j] = d1;
        }
        __syncwarp();
        {   // Pinf = W + phD@V^T
            float p0 = sW[i0*8 + j], p1 = sW[(i0+4)*8 + j];
            #pragma unroll
            for (int k = 0; k < 8; k++) {
                p0 += phD[i0*8 + k]     * sV[j*8 + k];
                p1 += phD[(i0+4)*8 + k] * sV[j*8 + k];
            }
            sPinf[i0*8 + j] = p0;  sPinf[(i0+4)*8 + j] = p1;
        }
        __syncwarp();

        // ---- steady coefficients from Pinf (R5-validated math, fp32)
        {
            float s = 0.f, c = 0.f;
            #pragma unroll
            for (int k = 0; k < 8; k++) {
                s += Hs[i0*8 + k] * sPinf[k*8 + j];
                c += sPinf[qi*8 + k] * Hs[qj*8 + k];
            }
            stHC[l] = s;  stCHt[l] = c;
        }
        __syncwarp();
        if (l < 16) {
            float s = Rs[l];
            #pragma unroll
            for (int k = 0; k < 8; k++) s += stHC[(l >> 2)*8 + k] * Hs[(l & 3)*8 + k];
            stS[l] = s;
        }
        __syncwarp();
        if (l < 16) stCof[l] = cof4t<float>(stS, l);
        __syncwarp();
        {
            const float det  = stS[0]*stCof[0] + stS[1]*stCof[1] + stS[2]*stCof[2] + stS[3]*stCof[3];
            const float rdet = 1.f / det;
            float s = 0.f;
            #pragma unroll
            for (int k = 0; k < 4; k++) s += stCHt[qi*4 + k] * stCof[k*4 + qj];
            stK[l] = s * rdet;
        }
        __syncwarp();
        {
            float m0 = 0.f, m1 = 0.f;
            #pragma unroll
            for (int k = 0; k < 4; k++) {
                const float hkj = Hs[k*8 + j];
                m0 += stK[i0*4 + k]     * hkj;
                m1 += stK[(i0+4)*4 + k] * hkj;
            }
            stM[i0*8 + j]     = (i0 == j     ? 1.f : 0.f) - m0;
            stM[(i0+4)*8 + j] = (i0 + 4 == j ? 1.f : 0.f) - m1;
        }
        __syncwarp();
        {
            float a0 = 0.f, a1 = 0.f, s0 = 0.f, s1 = 0.f;
            #pragma unroll
            for (int k = 0; k < 8; k++) {
                const float fkj = Fs[k*8 + j];
                a0 += stM[i0*8 + k]     * fkj;
                a1 += stM[(i0+4)*8 + k] * fkj;
            }
            #pragma unroll
            for (int k = 0; k < 4; k++) {
                const float hckj = stHC[k*8 + j];
                s0 += stK[i0*4 + k]     * hckj;
                s1 += stK[(i0+4)*4 + k] * hckj;
            }
            g_MK[T_EXACT*96 + l]      = a0;
            g_MK[T_EXACT*96 + 32 + l] = a1;
            g_MK[T_EXACT*96 + 64 + l] = stK[l];
            g_U [T_EXACT*64 + l]      = sPinf[i0*8 + j]     - s0;
            g_U [T_EXACT*64 + 32 + l] = sPinf[(i0+4)*8 + j] - s1;
        }
        __syncwarp();

        // ---- 6 super-steps with Phi^32: sP[j+1] = W32 + V32 sP[j](I+U32 sP[j])^-1 V32^T
        #pragma unroll 1
        for (int sj = 0; sj < NSUPER; sj++) {
            const float* Pj = sP[sj];
            {
                float s0 = 0.f, s1 = 0.f;
                #pragma unroll
                for (int k = 0; k < 8; k++) {
                    const float pkj = Pj[k*8 + j];
                    s0 += U32[i0*8 + k]     * pkj;
                    s1 += U32[(i0+4)*8 + k] * pkj;
                }
                phA[i0*8 + j]     = s0 + (i0 == j     ? 1.f : 0.f);
                phA[(i0+4)*8 + j] = s1 + (i0 + 4 == j ? 1.f : 0.f);
            }
            __syncwarp();
            inv8x8_f(phA, phT, l);
            __syncwarp();
            {   // phB = Pj@T
                float b0 = 0.f, b1 = 0.f;
                #pragma unroll
                for (int k = 0; k < 8; k++) {
                    const float tkj = phT[k*8 + j];
                    b0 += Pj[i0*8 + k]     * tkj;
                    b1 += Pj[(i0+4)*8 + k] * tkj;
                }
                phB[i0*8 + j] = b0;  phB[(i0+4)*8 + j] = b1;
            }
            __syncwarp();
            {   // phD = V32@phB
                float d0 = 0.f, d1 = 0.f;
                #pragma unroll
                for (int k = 0; k < 8; k++) {
                    const float bkj = phB[k*8 + j];
                    d0 += V32[i0*8 + k]     * bkj;
                    d1 += V32[(i0+4)*8 + k] * bkj;
                }
                phD[i0*8 + j] = d0;  phD[(i0+4)*8 + j] = d1;
            }
            __syncwarp();
            {   // sP[sj+1] = W32 + phD@V32^T
                float p0 = W32[i0*8 + j], p1 = W32[(i0+4)*8 + j];
                #pragma unroll
                for (int k = 0; k < 8; k++) {
                    p0 += phD[i0*8 + k]     * V32[j*8 + k];
                    p1 += phD[(i0+4)*8 + k] * V32[j*8 + k];
                }
                sP[sj+1][i0*8 + j] = p0;  sP[sj+1][(i0+4)*8 + j] = p1;
            }
            __syncwarp();
        }
    }
    __syncthreads();

    // ---------------- warps 1..7: parallel exact chains ----------------
    if (wid >= 1 && wid <= NCHAIN) {
        const int w   = wid;
        const int t0  = (w - 1) * SUPW;
        const int len = (t0 + SUPW <= T_EXACT) ? SUPW : (T_EXACT - t0);

        float* cw  = cw_all[w - 1];
        float* FPw = cw;          float* HCw = cw + 64;
        float* CHw = cw + 96;     float* Sw  = cw + 128;
        float* Cfw = cw + 144;    float* Kw  = cw + 160;
        float* Ww  = cw + 192;    float* Mw  = cw + 224;
        float* Pw  = sP[w - 1];

        const int i0 = l >> 3, j = l & 7;
        const int qi = l >> 2, qj = l & 3;

        #pragma unroll 1
        for (int s = 0; s < len; s++) {
            const int t = t0 + s;
            {   // s1: FP = F@P, HC = H@P, CHt = P@H^T
                float fp0 = 0.f, fp1 = 0.f, hc = 0.f, cht = 0.f;
                #pragma unroll
                for (int k = 0; k < 8; k++) {
                    const float pkj = Pw[k*8 + j];
                    fp0 += Fs[i0*8 + k]     * pkj;
                    fp1 += Fs[(i0+4)*8 + k] * pkj;
                    hc  += Hs[i0*8 + k]     * pkj;
                    cht += Pw[qi*8 + k] * Hs[qj*8 + k];
                }
                FPw[l] = fp0;  FPw[32 + l] = fp1;
                HCw[l] = hc;   CHw[l] = cht;
            }
            __syncwarp();
            if (l < 16) {
                float sv = Rs[l];
                #pragma unroll
                for (int k = 0; k < 8; k++) sv += HCw[(l >> 2)*8 + k] * Hs[(l & 3)*8 + k];
                Sw[l] = sv;
            }
            __syncwarp();
            if (l < 16) Cfw[l] = cof4t<float>(Sw, l);
            __syncwarp();
            {
                const float det  = Sw[0]*Cfw[0] + Sw[1]*Cfw[1] + Sw[2]*Cfw[2] + Sw[3]*Cfw[3];
                const float rdet = 1.0f / det;
                float sv = 0.f;
                #pragma unroll
                for (int k = 0; k < 4; k++) sv += CHw[qi*4 + k] * Cfw[k*4 + qj];
                Kw[l] = sv * rdet;
            }
            __syncwarp();
            float u0, u1;
            {
                float su0 = 0.f, sm0 = 0.f, su1 = 0.f, sm1 = 0.f, wv = 0.f;
                #pragma unroll
                for (int k = 0; k < 4; k++) {
                    const float hckj = HCw[k*8 + j], hskj = Hs[k*8 + j];
                    su0 += Kw[i0*4 + k]     * hckj;
                    sm0 += Kw[i0*4 + k]     * hskj;
                    su1 += Kw[(i0+4)*4 + k] * hckj;
                    sm1 += Kw[(i0+4)*4 + k] * hskj;
                }
                #pragma unroll
                for (int k = 0; k < 8; k++) wv += Fs[qi*8 + k] * Kw[k*4 + qj];
                u0 = Pw[l] - su0;
                u1 = Pw[32 + l] - su1;
                Mw[l]      = (i0 == j     ? 1.0f : 0.0f) - sm0;
                Mw[32 + l] = (i0 + 4 == j ? 1.0f : 0.0f) - sm1;
                Ww[l] = wv;
            }
            __syncwarp();
            {
                float a0, a1;
                if (t == 0) { a0 = Mw[l];  a1 = Mw[32 + l]; }
                else {
                    a0 = 0.f;  a1 = 0.f;
                    #pragma unroll
                    for (int k = 0; k < 8; k++) {
                        const float fkj = Fs[k*8 + j];
                        a0 += Mw[i0*8 + k]     * fkj;
                        a1 += Mw[(i0+4)*8 + k] * fkj;
                    }
                }
                g_MK[t*96 + l]      = a0;
                g_MK[t*96 + 32 + l] = a1;
                g_MK[t*96 + 64 + l] = Kw[l];
                g_U [t*64 + l]      = u0;
                g_U [t*64 + 32 + l] = u1;

                const float w00 = Ww[i0*4+0],     w01 = Ww[i0*4+1],     w02 = Ww[i0*4+2],     w03 = Ww[i0*4+3];
                const float w10 = Ww[(i0+4)*4+0], w11 = Ww[(i0+4)*4+1], w12 = Ww[(i0+4)*4+2], w13 = Ww[(i0+4)*4+3];
                float p0 = Qs[l], p1 = Qs[32 + l];
                #pragma unroll
                for (int k = 0; k < 8; k++) {
                    const float h0 = HCw[k], h1 = HCw[8+k], h2 = HCw[16+k], h3 = HCw[24+k];
                    const float fjk = Fs[j*8 + k];
                    const float fu0 = FPw[i0*8 + k]     - (w00*h0 + w01*h1 + w02*h2 + w03*h3);
                    const float fu1 = FPw[(i0+4)*8 + k] - (w10*h0 + w11*h1 + w12*h2 + w13*h3);
                    p0 += fu0 * fjk;
                    p1 += fu1 * fjk;
                }
                Pw[l] = p0;  Pw[32 + l] = p1;
            }
            __syncwarp();
        }
    }
}

// ---------------------------------------------------------------------------
// Main kernel — R2's proven structure: 32 mean blocks + 1000 one-tile bcast.
// ---------------------------------------------------------------------------
__global__ void __launch_bounds__(THREADS, 4) main_kernel(
    const float* __restrict__ obs,
    const float* __restrict__ init_mean,
    float* __restrict__ out)
{
    const int tid = threadIdx.x;

    if (blockIdx.x < NB_MEAN) {
        // ------------------ mean recursion (2 threads/batch) ------------------
        __shared__ float coef[CHUNK * 96];
        const int gtid = blockIdx.x * THREADS + tid;
        const int b    = gtid >> 1;
        const int half = gtid & 1;

        float st[8];
        #pragma unroll
        for (int i = 0; i < 8; i++) st[i] = init_mean[b*8 + i];

        for (int c = 0; c < T_STEPS / CHUNK; c++) {
            if (c < NCHUNK_EXACT) {
                __syncthreads();
                if (tid < CHUNK*24)
                    reinterpret_cast<float4*>(coef)[tid] =
                        reinterpret_cast<const float4*>(&g_MK[c*(CHUNK*96)])[tid];
                __syncthreads();
            } else if (c == NCHUNK_EXACT) {
                __syncthreads();
                if (tid < 24)
                    reinterpret_cast<float4*>(coef)[tid] =
                        reinterpret_cast<const float4*>(&g_MK[T_EXACT*96])[tid];
                __syncthreads();
            }
            #pragma unroll
            for (int u = 0; u < CHUNK; u++) {
                const int t = c*CHUNK + u;
                const float* Cs = &coef[(c < NCHUNK_EXACT ? u : 0) * 96];

                const float4 zv = *reinterpret_cast<const float4*>(
                    &obs[((size_t)t*BATCH + b) * 4]);

                float y[4];
                #pragma unroll
                for (int r = 0; r < 4; r++) {
                    const int row = half*4 + r;
                    const float4 a0 = *reinterpret_cast<const float4*>(&Cs[row*8]);
                    const float4 a1 = *reinterpret_cast<const float4*>(&Cs[row*8 + 4]);
                    const float4 kk = *reinterpret_cast<const float4*>(&Cs[64 + row*4]);
                    y[r] = a0.x*st[0] + a0.y*st[1] + a0.z*st[2] + a0.w*st[3]
                         + a1.x*st[4] + a1.y*st[5] + a1.z*st[6] + a1.w*st[7]
                         + kk.x*zv.x + kk.y*zv.y + kk.z*zv.z + kk.w*zv.w;
                }

                __stcs(reinterpret_cast<float4*>(&out[((size_t)t*BATCH + b)*8 + half*4]),
                       make_float4(y[0], y[1], y[2], y[3]));

                const float o0 = __shfl_xor_sync(FULLMASK, y[0], 1);
                const float o1 = __shfl_xor_sync(FULLMASK, y[1], 1);
                const float o2 = __shfl_xor_sync(FULLMASK, y[2], 1);
                const float o3 = __shfl_xor_sync(FULLMASK, y[3], 1);
                st[0] = half ? o0   : y[0];
                st[1] = half ? o1   : y[1];
                st[2] = half ? o2   : y[2];
                st[3] = half ? o3   : y[3];
                st[4] = half ? y[0] : o0;
                st[5] = half ? y[1] : o1;
                st[6] = half ? y[2] : o2;
                st[7] = half ? y[3] : o3;
            }
        }
    } else {
        // ------------------ covariance broadcast: one tile per block ------------------
        const int t  = (int)blockIdx.x - NB_MEAN;            // 0..999
        const int tc = (t < T_EXACT) ? t : T_EXACT;
        const float4 val = reinterpret_cast<const float4*>(g_U)[tc*16 + (tid & 15)];

        float4* dst = reinterpret_cast<float4*>(out + MEANS_ELEMS)
                    + (size_t)t * 65536 + tid;
        #pragma unroll 8
        for (int it = 0; it < 256; it++) {
            __stcs(dst, val);
            dst += THREADS;
        }
    }
}

// ---------------------------------------------------------------------------
extern "C" void kernel_launch(void* const* d_in, const int* in_sizes, int n_in,
                              void* d_out, int out_size)
{
    const float* obs       = (const float*)d_in[0];
    const float* F         = (const float*)d_in[1];
    const float* H         = (const float*)d_in[2];
    const float* Q         = (const float*)d_in[3];
    const float* R         = (const float*)d_in[4];
    const float* init_mean = (const float*)d_in[5];
    const float* init_cov  = (const float*)d_in[6];
    float* out = (float*)d_out;

    setup_kernel<<<1, 256>>>(F, H, Q, R, init_cov);
    main_kernel<<<NB_TOTAL, THREADS>>>(obs, init_mean, out);
}